// round 3
// baseline (speedup 1.0000x reference)
#include <cuda_runtime.h>
#include <math.h>

#define N_SP 4096
#define C_IN 256
#define CQ   32
#define BATCH 4

// d_out layout (floats): q[0], k[524288], v[1048576], attended[5242880]
#define Q_OFF 0
#define K_OFF 524288
#define V_OFF 1048576
#define A_OFF 5242880

typedef unsigned long long u64;

__device__ __forceinline__ u64 pack2(float x, float y) {
    u64 r; asm("mov.b64 %0, {%1,%2};" : "=l"(r) : "f"(x), "f"(y)); return r;
}
__device__ __forceinline__ void unpack2(u64 v, float &x, float &y) {
    asm("mov.b64 {%0,%1}, %2;" : "=f"(x), "=f"(y) : "l"(v));
}
__device__ __forceinline__ void fma2(u64 &d, u64 a, u64 b) {
    asm("fma.rn.f32x2 %0, %1, %2, %3;" : "=l"(d) : "l"(a), "l"(b), "l"(d));
}
__device__ __forceinline__ void mul2(u64 &d, u64 a, u64 b) {
    asm("mul.rn.f32x2 %0, %1, %2;" : "=l"(d) : "l"(a), "l"(b));
}

// Scratch (device globals: allowed; no dynamic allocation)
__device__ float g_attn_out[BATCH * C_IN * N_SP];  // 16 MB
__device__ float g_proj[BATCH * C_IN * N_SP];      // 16 MB

// ---------------------------------------------------------------------------
// Kernel 1: QKV projections.  Out[o][n] = sum_c W[o][c] * x[b][c][n]
// Grid: (64 ntiles, 10 otiles, 4 b). Block 256. Tile: 32 o x 64 n, K-tile 32.
// ---------------------------------------------------------------------------
__global__ __launch_bounds__(256) void qkv_kernel(
    const float* __restrict__ x,
    const float* __restrict__ Wq,
    const float* __restrict__ Wk,
    const float* __restrict__ Wv,
    float* __restrict__ out)
{
    __shared__ float Wt[32 * 33];
    __shared__ float Xt[32 * 68];

    const int b  = blockIdx.z;
    const int ot = blockIdx.y;
    const int n0 = blockIdx.x * 64;

    const float* W;
    float* dst;
    if (ot == 0)      { W = Wq; dst = out + Q_OFF + (size_t)b * CQ   * N_SP; }
    else if (ot == 1) { W = Wk; dst = out + K_OFF + (size_t)b * CQ   * N_SP; }
    else              { W = Wv + (ot - 2) * 32 * C_IN;
                        dst = out + V_OFF + (size_t)b * C_IN * N_SP + (size_t)(ot - 2) * 32 * N_SP; }

    const float* xb = x + (size_t)b * C_IN * N_SP;

    const int t    = threadIdx.x;
    const int lane = t & 31;
    const int warp = t >> 5;

    u64 acc[4] = {0ull, 0ull, 0ull, 0ull};

    for (int c0 = 0; c0 < C_IN; c0 += 32) {
        for (int i = t; i < 1024; i += 256) {
            int o = i >> 5, c = i & 31;
            Wt[o * 33 + c] = W[o * C_IN + c0 + c];
        }
        for (int i = t; i < 2048; i += 256) {
            int c = i >> 6, n = i & 63;
            Xt[c * 68 + n] = xb[(size_t)(c0 + c) * N_SP + n0 + n];
        }
        __syncthreads();

#pragma unroll
        for (int c = 0; c < 32; c++) {
            float wv = Wt[lane * 33 + c];
            u64 ww = pack2(wv, wv);
            const ulonglong2 x0 = *(const ulonglong2*)&Xt[c * 68 + warp * 8];
            const ulonglong2 x1 = *(const ulonglong2*)&Xt[c * 68 + warp * 8 + 4];
            fma2(acc[0], ww, x0.x);
            fma2(acc[1], ww, x0.y);
            fma2(acc[2], ww, x1.x);
            fma2(acc[3], ww, x1.y);
        }
        __syncthreads();
    }

    float r[8];
    unpack2(acc[0], r[0], r[1]); unpack2(acc[1], r[2], r[3]);
    unpack2(acc[2], r[4], r[5]); unpack2(acc[3], r[6], r[7]);
    float* drow = dst + (size_t)lane * N_SP + n0 + warp * 8;
    *(float4*)(drow)     = make_float4(r[0], r[1], r[2], r[3]);
    *(float4*)(drow + 4) = make_float4(r[4], r[5], r[6], r[7]);
}

// ---------------------------------------------------------------------------
// Kernel 2: flash attention with packed f32x2 FMA.
// Block: 32 query rows, 256 threads. lane = query row, warp = 32-wide c-chunk.
// ---------------------------------------------------------------------------
__global__ __launch_bounds__(256) void attn_kernel(
    const float* __restrict__ qbuf,
    const float* __restrict__ kbuf,
    const float* __restrict__ vbuf)
{
    __shared__ float Qs[32 * 34];    // [n][c], pad 34 (even -> 8B-aligned pairs)
    __shared__ float Ks[32 * 36];    // [m][c], pad 36 (16B-aligned rows)
    __shared__ float Ss[32 * 33];    // [n][m]
    __shared__ float Vs[32 * 260];   // [m][c], pad 260 (16B-aligned rows)
    __shared__ float m_row[32], l_row[32], a_row[32];

    const int b  = blockIdx.y;
    const int n0 = blockIdx.x * 32;
    const int t    = threadIdx.x;
    const int lane = t & 31;
    const int warp = t >> 5;

    const float scale = 0.1767766952966369f;  // 32^-0.5

    const float* q = qbuf + (size_t)b * CQ   * N_SP;
    const float* k = kbuf + (size_t)b * CQ   * N_SP;
    const float* v = vbuf + (size_t)b * C_IN * N_SP;

    // Load Q tile (pre-scaled) to smem
    for (int i = t; i < 1024; i += 256) {
        int c = i >> 5, n = i & 31;
        Qs[n * 34 + c] = q[(size_t)c * N_SP + n0 + n] * scale;
    }
    if (t < 32) { m_row[t] = -1e30f; l_row[t] = 0.f; }
    __syncthreads();

    // Hoist this thread's query row into packed registers (16 c-pairs)
    u64 qp[16];
#pragma unroll
    for (int j = 0; j < 16; j++) qp[j] = *(const u64*)&Qs[lane * 34 + 2 * j];

    u64 o[16];
#pragma unroll
    for (int j = 0; j < 16; j++) o[j] = 0ull;

    for (int m0 = 0; m0 < N_SP; m0 += 32) {
        // K tile: [m][c], thread loads 4 c-values for one m, STS.128
        {
            const int m  = t & 31;
            const int cc = t >> 5;           // 0..7 -> c base 4*cc
            float kv0 = k[(size_t)(4 * cc + 0) * N_SP + m0 + m];
            float kv1 = k[(size_t)(4 * cc + 1) * N_SP + m0 + m];
            float kv2 = k[(size_t)(4 * cc + 2) * N_SP + m0 + m];
            float kv3 = k[(size_t)(4 * cc + 3) * N_SP + m0 + m];
            *(float4*)&Ks[m * 36 + 4 * cc] = make_float4(kv0, kv1, kv2, kv3);
        }
        // V tile: [m][c] (32 x 256), 8 iterations of 4 gathers + STS.128
#pragma unroll
        for (int it = 0; it < 8; it++) {
            const int flat = t + it * 256;
            const int m  = flat & 31;
            const int cc = flat >> 5;        // 0..63 -> c base 4*cc
            float v0 = v[(size_t)(4 * cc + 0) * N_SP + m0 + m];
            float v1 = v[(size_t)(4 * cc + 1) * N_SP + m0 + m];
            float v2 = v[(size_t)(4 * cc + 2) * N_SP + m0 + m];
            float v3 = v[(size_t)(4 * cc + 3) * N_SP + m0 + m];
            *(float4*)&Vs[m * 260 + 4 * cc] = make_float4(v0, v1, v2, v3);
        }
        __syncthreads();

        // S: thread computes rows n=lane, cols m = warp*4 .. +3 (packed over c)
        {
            const int mb = warp * 4;
            u64 s0 = 0ull, s1 = 0ull, s2 = 0ull, s3 = 0ull;
#pragma unroll
            for (int j = 0; j < 8; j++) {
                const ulonglong2 k0 = *(const ulonglong2*)&Ks[(mb + 0) * 36 + 4 * j];
                const ulonglong2 k1 = *(const ulonglong2*)&Ks[(mb + 1) * 36 + 4 * j];
                const ulonglong2 k2 = *(const ulonglong2*)&Ks[(mb + 2) * 36 + 4 * j];
                const ulonglong2 k3 = *(const ulonglong2*)&Ks[(mb + 3) * 36 + 4 * j];
                fma2(s0, qp[2 * j], k0.x); fma2(s0, qp[2 * j + 1], k0.y);
                fma2(s1, qp[2 * j], k1.x); fma2(s1, qp[2 * j + 1], k1.y);
                fma2(s2, qp[2 * j], k2.x); fma2(s2, qp[2 * j + 1], k2.y);
                fma2(s3, qp[2 * j], k3.x); fma2(s3, qp[2 * j + 1], k3.y);
            }
            float a0, a1;
            unpack2(s0, a0, a1); Ss[lane * 33 + mb + 0] = a0 + a1;
            unpack2(s1, a0, a1); Ss[lane * 33 + mb + 1] = a0 + a1;
            unpack2(s2, a0, a1); Ss[lane * 33 + mb + 2] = a0 + a1;
            unpack2(s3, a0, a1); Ss[lane * 33 + mb + 3] = a0 + a1;
        }
        __syncthreads();

        // Online softmax: warp w owns rows 4w..4w+3 (lane-parallel over m)
#pragma unroll
        for (int rr = 0; rr < 4; rr++) {
            const int row = warp * 4 + rr;
            float s = Ss[row * 33 + lane];
            float mx = s;
#pragma unroll
            for (int off = 16; off; off >>= 1)
                mx = fmaxf(mx, __shfl_xor_sync(0xffffffffu, mx, off));
            float mold = m_row[row];
            float mnew = fmaxf(mold, mx);
            float p = __expf(s - mnew);
            float ps = p;
#pragma unroll
            for (int off = 16; off; off >>= 1)
                ps += __shfl_xor_sync(0xffffffffu, ps, off);
            Ss[row * 33 + lane] = p;
            if (lane == 0) {
                float alpha = __expf(mold - mnew);
                l_row[row] = alpha * l_row[row] + ps;
                m_row[row] = mnew;
                a_row[row] = alpha;
            }
        }
        __syncthreads();

        // Rescale + accumulate (packed over c)
        {
            float alpha = a_row[lane];
            u64 al = pack2(alpha, alpha);
#pragma unroll
            for (int j = 0; j < 16; j++) mul2(o[j], o[j], al);

            const int cb = warp * 32;
#pragma unroll
            for (int mm = 0; mm < 32; mm++) {
                float p = Ss[lane * 33 + mm];
                u64 pp = pack2(p, p);
#pragma unroll
                for (int j = 0; j < 8; j++) {
                    const ulonglong2 vv = *(const ulonglong2*)&Vs[mm * 260 + cb + 4 * j];
                    fma2(o[2 * j],     pp, vv.x);
                    fma2(o[2 * j + 1], pp, vv.y);
                }
            }
        }
        __syncthreads();
    }

    const float inv = 1.f / l_row[lane];
    float* ob = g_attn_out + (size_t)b * C_IN * N_SP;
#pragma unroll
    for (int j = 0; j < 16; j++) {
        float a0, a1;
        unpack2(o[j], a0, a1);
        ob[(size_t)(warp * 32 + 2 * j)     * N_SP + n0 + lane] = a0 * inv;
        ob[(size_t)(warp * 32 + 2 * j + 1) * N_SP + n0 + lane] = a1 * inv;
    }
}

// ---------------------------------------------------------------------------
// Kernel 3: output projection.  proj[o][n] = sum_c Wp[o][c] * attn_out[c][n]
// ---------------------------------------------------------------------------
__global__ __launch_bounds__(256) void proj_kernel(const float* __restrict__ Wp)
{
    __shared__ float Wt[32 * 33];
    __shared__ float Xt[32 * 68];

    const int b  = blockIdx.z;
    const int ot = blockIdx.y;
    const int n0 = blockIdx.x * 64;

    const float* W  = Wp + ot * 32 * C_IN;
    const float* xb = g_attn_out + (size_t)b * C_IN * N_SP;
    float* dst      = g_proj + (size_t)b * C_IN * N_SP + (size_t)ot * 32 * N_SP;

    const int t    = threadIdx.x;
    const int lane = t & 31;
    const int warp = t >> 5;

    u64 acc[4] = {0ull, 0ull, 0ull, 0ull};

    for (int c0 = 0; c0 < C_IN; c0 += 32) {
        for (int i = t; i < 1024; i += 256) {
            int o = i >> 5, c = i & 31;
            Wt[o * 33 + c] = W[o * C_IN + c0 + c];
        }
        for (int i = t; i < 2048; i += 256) {
            int c = i >> 6, n = i & 63;
            Xt[c * 68 + n] = xb[(size_t)(c0 + c) * N_SP + n0 + n];
        }
        __syncthreads();

#pragma unroll
        for (int c = 0; c < 32; c++) {
            float wv = Wt[lane * 33 + c];
            u64 ww = pack2(wv, wv);
            const ulonglong2 x0 = *(const ulonglong2*)&Xt[c * 68 + warp * 8];
            const ulonglong2 x1 = *(const ulonglong2*)&Xt[c * 68 + warp * 8 + 4];
            fma2(acc[0], ww, x0.x);
            fma2(acc[1], ww, x0.y);
            fma2(acc[2], ww, x1.x);
            fma2(acc[3], ww, x1.y);
        }
        __syncthreads();
    }

    float r[8];
    unpack2(acc[0], r[0], r[1]); unpack2(acc[1], r[2], r[3]);
    unpack2(acc[2], r[4], r[5]); unpack2(acc[3], r[6], r[7]);
    float* drow = dst + (size_t)lane * N_SP + n0 + warp * 8;
    *(float4*)(drow)     = make_float4(r[0], r[1], r[2], r[3]);
    *(float4*)(drow + 4) = make_float4(r[4], r[5], r[6], r[7]);
}

// ---------------------------------------------------------------------------
// Kernel 4: InstanceNorm (affine=False, biased var) + residual.
// ---------------------------------------------------------------------------
__global__ __launch_bounds__(256) void norm_kernel(
    const float* __restrict__ x,
    float* __restrict__ att_out)
{
    __shared__ float red[16];

    const size_t bc = blockIdx.x;
    const float4* p4 = (const float4*)(g_proj + bc * N_SP);
    const float4* x4 = (const float4*)(x + bc * N_SP);
    float4* o4       = (float4*)(att_out + bc * N_SP);

    const int t    = threadIdx.x;
    const int lane = t & 31;
    const int warp = t >> 5;

    float4 vals[4];
    float s = 0.f, sq = 0.f;
#pragma unroll
    for (int i = 0; i < 4; i++) {
        float4 v = p4[i * 256 + t];
        vals[i] = v;
        s  += v.x + v.y + v.z + v.w;
        sq += v.x * v.x + v.y * v.y + v.z * v.z + v.w * v.w;
    }
#pragma unroll
    for (int off = 16; off; off >>= 1) {
        s  += __shfl_xor_sync(0xffffffffu, s, off);
        sq += __shfl_xor_sync(0xffffffffu, sq, off);
    }
    if (lane == 0) { red[warp] = s; red[8 + warp] = sq; }
    __syncthreads();
    if (t == 0) {
        float ts = 0.f, tq = 0.f;
        for (int i = 0; i < 8; i++) { ts += red[i]; tq += red[8 + i]; }
        red[0] = ts; red[8] = tq;
    }
    __syncthreads();

    const float mean = red[0] * (1.f / N_SP);
    float var = red[8] * (1.f / N_SP) - mean * mean;
    const float rstd = rsqrtf(var + 1e-5f);

#pragma unroll
    for (int i = 0; i < 4; i++) {
        float4 v  = vals[i];
        float4 xr = x4[i * 256 + t];
        float4 r;
        r.x = (v.x - mean) * rstd + xr.x;
        r.y = (v.y - mean) * rstd + xr.y;
        r.z = (v.z - mean) * rstd + xr.z;
        r.w = (v.w - mean) * rstd + xr.w;
        o4[i * 256 + t] = r;
    }
}

// ---------------------------------------------------------------------------
extern "C" void kernel_launch(void* const* d_in, const int* in_sizes, int n_in,
                              void* d_out, int out_size)
{
    const float* x  = (const float*)d_in[0];
    const float* Wq = (const float*)d_in[1];
    const float* Wk = (const float*)d_in[2];
    const float* Wv = (const float*)d_in[3];
    const float* Wp = (const float*)d_in[4];
    float* out = (float*)d_out;

    qkv_kernel<<<dim3(64, 10, BATCH), 256>>>(x, Wq, Wk, Wv, out);
    attn_kernel<<<dim3(N_SP / 32, BATCH), 256>>>(out + Q_OFF, out + K_OFF, out + V_OFF);
    proj_kernel<<<dim3(64, 8, BATCH), 256>>>(Wp);
    norm_kernel<<<BATCH * C_IN, 256>>>(x, out + A_OFF);
}

// round 5
// speedup vs baseline: 5.2713x; 5.2713x over previous
#include <cuda_runtime.h>
#include <math.h>
#include <stdint.h>

#define N_SP 4096
#define C_IN 256
#define CQ   32
#define BATCH 4

// d_out layout (floats): q[0], k[524288], v[1048576], attended[5242880]
#define Q_OFF 0
#define K_OFF 524288
#define V_OFF 1048576
#define A_OFF 5242880

// Scratch (device globals: allowed; no dynamic allocation)
__device__ float g_attn_out[BATCH * C_IN * N_SP];  // 16 MB
__device__ float g_proj[BATCH * C_IN * N_SP];      // 16 MB

// ---------------------------------------------------------------------------
// mma.sync tf32 helpers (sm_80+ generic PTX -> legal at compute_103)
// ---------------------------------------------------------------------------
__device__ __forceinline__ uint32_t f2tf32(float f) {
    uint32_t r;
    asm("cvt.rna.tf32.f32 %0, %1;" : "=r"(r) : "f"(f));
    return r;
}
__device__ __forceinline__ void mma_tf32(
    float& d0, float& d1, float& d2, float& d3,
    uint32_t a0, uint32_t a1, uint32_t a2, uint32_t a3,
    uint32_t b0, uint32_t b1)
{
    asm volatile(
        "mma.sync.aligned.m16n8k8.row.col.f32.tf32.tf32.f32 "
        "{%0,%1,%2,%3}, {%4,%5,%6,%7}, {%8,%9}, {%0,%1,%2,%3};"
        : "+f"(d0), "+f"(d1), "+f"(d2), "+f"(d3)
        : "r"(a0), "r"(a1), "r"(a2), "r"(a3), "r"(b0), "r"(b1));
}

// ---------------------------------------------------------------------------
// Kernel 1: QKV projections (scalar fp32; exact outputs).
// ---------------------------------------------------------------------------
__global__ __launch_bounds__(256) void qkv_kernel(
    const float* __restrict__ x,
    const float* __restrict__ Wq,
    const float* __restrict__ Wk,
    const float* __restrict__ Wv,
    float* __restrict__ out)
{
    __shared__ float Wt[32 * 33];
    __shared__ float Xt[32 * 68];

    const int b  = blockIdx.z;
    const int ot = blockIdx.y;
    const int n0 = blockIdx.x * 64;

    const float* W;
    float* dst;
    if (ot == 0)      { W = Wq; dst = out + Q_OFF + (size_t)b * CQ   * N_SP; }
    else if (ot == 1) { W = Wk; dst = out + K_OFF + (size_t)b * CQ   * N_SP; }
    else              { W = Wv + (ot - 2) * 32 * C_IN;
                        dst = out + V_OFF + (size_t)b * C_IN * N_SP + (size_t)(ot - 2) * 32 * N_SP; }

    const float* xb = x + (size_t)b * C_IN * N_SP;
    const int t = threadIdx.x, lane = t & 31, warp = t >> 5;

    float acc[8];
#pragma unroll
    for (int i = 0; i < 8; i++) acc[i] = 0.f;

    for (int c0 = 0; c0 < C_IN; c0 += 32) {
        for (int i = t; i < 1024; i += 256) {
            int o = i >> 5, c = i & 31;
            Wt[o * 33 + c] = W[o * C_IN + c0 + c];
        }
        for (int i = t; i < 2048; i += 256) {
            int c = i >> 6, n = i & 63;
            Xt[c * 68 + n] = xb[(size_t)(c0 + c) * N_SP + n0 + n];
        }
        __syncthreads();
#pragma unroll
        for (int c = 0; c < 32; c++) {
            float wv = Wt[lane * 33 + c];
            const float4 xv0 = *(const float4*)&Xt[c * 68 + warp * 8];
            const float4 xv1 = *(const float4*)&Xt[c * 68 + warp * 8 + 4];
            acc[0] += wv * xv0.x; acc[1] += wv * xv0.y;
            acc[2] += wv * xv0.z; acc[3] += wv * xv0.w;
            acc[4] += wv * xv1.x; acc[5] += wv * xv1.y;
            acc[6] += wv * xv1.z; acc[7] += wv * xv1.w;
        }
        __syncthreads();
    }
    float* drow = dst + (size_t)lane * N_SP + n0 + warp * 8;
    *(float4*)(drow)     = make_float4(acc[0], acc[1], acc[2], acc[3]);
    *(float4*)(drow + 4) = make_float4(acc[4], acc[5], acc[6], acc[7]);
}

// ---------------------------------------------------------------------------
// Kernel 2: flash attention via mma.sync tf32.
// Grid (32 q-tiles, 4 batch). CTA = 256 threads = 8 warps, 1 CTA/SM.
// Q-tile = 128 rows. Loop 32 KV tiles of 128 m.
//
//  GEMM1 (fused with softmax): warp w owns q-rows 16w..16w+15.
//    Per 8-col m-fragment: 4 mma (k=32) -> p=expf(s) -> l += -> tf32 ->
//    store into Pt[m][perm(q)] (transposed P, vector-load-ready layout).
//  GEMM2: O^T[c][q] += V * P^T. Warp (cg=w%4, qg=w/4): 64 c-rows x 64 q-cols,
//    A = V fragments from Vs[c][m] (LDS.32, conflict-free),
//    B = Pt fragments via LDS.128 (4 n-frags per load, stride 136 -> no bank
//    conflicts). O accum: 128 regs/thread, persistent across tiles.
//  Epilogue: divide by l (no online rescale needed: exp without max, s bounded).
//
// SMEM (floats): Vs[256*132] | Ks[32*132] | Pt[128*136]  = 221696 bytes.
// ---------------------------------------------------------------------------
#define VS_STRIDE 132
#define KS_STRIDE 132
#define PT_STRIDE 136
#define VS_FLOATS (256 * VS_STRIDE)
#define KS_FLOATS (32 * KS_STRIDE)
#define PT_FLOATS (128 * PT_STRIDE)
#define ATTN_SMEM_BYTES ((VS_FLOATS + KS_FLOATS + PT_FLOATS) * 4)

// Pt column permutation: q = 32*Q + 8*f + g  ->  pos = 32*Q + 4*g + f
__device__ __forceinline__ int pt_pos(int q) {
    return ((q >> 5) << 5) + ((q & 7) << 2) + ((q >> 3) & 3);
}

__global__ __launch_bounds__(256, 1) void attn_kernel(
    const float* __restrict__ qbuf,
    const float* __restrict__ kbuf,
    const float* __restrict__ vbuf)
{
    extern __shared__ float smem[];
    float* Vs = smem;
    float* Ks = smem + VS_FLOATS;
    float* Pt = smem + VS_FLOATS + KS_FLOATS;
    __shared__ float l_sm[128];

    const int t    = threadIdx.x;
    const int w    = t >> 5;
    const int lane = t & 31;
    const int gr   = lane >> 2;   // group row (0..7)
    const int t4   = lane & 3;    // thread-in-group (0..3)

    const int b  = blockIdx.y;
    const int n0 = blockIdx.x * 128;
    const float scale = 0.1767766952966369f;  // 32^-0.5

    const float* q = qbuf + (size_t)b * CQ   * N_SP;
    const float* k = kbuf + (size_t)b * CQ   * N_SP;
    const float* v = vbuf + (size_t)b * C_IN * N_SP;

    // --- Q fragments (persistent): A[r][c] = q[c][n0+16w+r]*scale, tf32 ---
    uint32_t qa[4][4];
    {
        const int rA = n0 + 16 * w + gr;
        const int rB = rA + 8;
#pragma unroll
        for (int ks = 0; ks < 4; ks++) {
            const int c0 = 8 * ks + t4;
            qa[ks][0] = f2tf32(q[(size_t)c0 * N_SP + rA] * scale);
            qa[ks][1] = f2tf32(q[(size_t)c0 * N_SP + rB] * scale);
            qa[ks][2] = f2tf32(q[(size_t)(c0 + 4) * N_SP + rA] * scale);
            qa[ks][3] = f2tf32(q[(size_t)(c0 + 4) * N_SP + rB] * scale);
        }
    }

    // O^T accum: warp (cg, qg): c rows 64*cg + 0..63, q cols 64*qg + 0..63
    const int cg = w & 3;
    const int qg = w >> 2;
    float d[4][8][4];
#pragma unroll
    for (int mf = 0; mf < 4; mf++)
#pragma unroll
        for (int nf = 0; nf < 8; nf++)
#pragma unroll
            for (int j = 0; j < 4; j++) d[mf][nf][j] = 0.f;

    float l0 = 0.f, l1 = 0.f;
    const int posA = pt_pos(16 * w + gr);
    const int posB = pt_pos(16 * w + gr + 8);

    for (int it = 0; it < 32; it++) {
        const int m0 = it * 128;
        __syncthreads();  // protect Vs/Ks/Pt from previous tile's readers

        // --- stage K tile [32 c][128 m] -> Ks[c][m] (tf32) ---
#pragma unroll
        for (int i = 0; i < 4; i++) {
            const int fl = t + 256 * i;         // 1024 float4s
            const int c  = fl >> 5;
            const int j  = fl & 31;
            float4 kv = *(const float4*)&k[(size_t)c * N_SP + m0 + 4 * j];
            kv.x = __uint_as_float(f2tf32(kv.x));
            kv.y = __uint_as_float(f2tf32(kv.y));
            kv.z = __uint_as_float(f2tf32(kv.z));
            kv.w = __uint_as_float(f2tf32(kv.w));
            *(float4*)&Ks[c * KS_STRIDE + 4 * j] = kv;
        }
        // --- stage V tile [256 c][128 m] -> Vs[c][m] (tf32) ---
#pragma unroll
        for (int i = 0; i < 32; i++) {
            const int fl = t + 256 * i;         // 8192 float4s
            const int c  = fl >> 5;
            const int j  = fl & 31;
            float4 vv = *(const float4*)&v[(size_t)c * N_SP + m0 + 4 * j];
            vv.x = __uint_as_float(f2tf32(vv.x));
            vv.y = __uint_as_float(f2tf32(vv.y));
            vv.z = __uint_as_float(f2tf32(vv.z));
            vv.w = __uint_as_float(f2tf32(vv.w));
            *(float4*)&Vs[c * VS_STRIDE + 4 * j] = vv;
        }
        __syncthreads();

        // --- GEMM1 + softmax + Pt store (fused per m-fragment) ---
#pragma unroll
        for (int nf = 0; nf < 16; nf++) {
            float s0 = 0.f, s1 = 0.f, s2 = 0.f, s3 = 0.f;
#pragma unroll
            for (int ks = 0; ks < 4; ks++) {
                const uint32_t b0 = __float_as_uint(Ks[(8 * ks + t4) * KS_STRIDE + 8 * nf + gr]);
                const uint32_t b1 = __float_as_uint(Ks[(8 * ks + t4 + 4) * KS_STRIDE + 8 * nf + gr]);
                mma_tf32(s0, s1, s2, s3, qa[ks][0], qa[ks][1], qa[ks][2], qa[ks][3], b0, b1);
            }
            const float p0 = __expf(s0);
            const float p1 = __expf(s1);
            const float p2 = __expf(s2);
            const float p3 = __expf(s3);
            l0 += p0 + p1;
            l1 += p2 + p3;
            const int mrow = 8 * nf + 2 * t4;
            Pt[mrow * PT_STRIDE + posA]       = __uint_as_float(f2tf32(p0));
            Pt[(mrow + 1) * PT_STRIDE + posA] = __uint_as_float(f2tf32(p1));
            Pt[mrow * PT_STRIDE + posB]       = __uint_as_float(f2tf32(p2));
            Pt[(mrow + 1) * PT_STRIDE + posB] = __uint_as_float(f2tf32(p3));
        }
        __syncthreads();

        // --- GEMM2: O^T += V * P^T ---
#pragma unroll
        for (int ks = 0; ks < 16; ks++) {
            const float* pr0 = &Pt[(8 * ks + t4) * PT_STRIDE];
            const float* pr1 = &Pt[(8 * ks + t4 + 4) * PT_STRIDE];
            const float4 b0a = *(const float4*)&pr0[64 * qg + 4 * gr];
            const float4 b1a = *(const float4*)&pr1[64 * qg + 4 * gr];
            const float4 b0b = *(const float4*)&pr0[64 * qg + 32 + 4 * gr];
            const float4 b1b = *(const float4*)&pr1[64 * qg + 32 + 4 * gr];
#pragma unroll
            for (int mf = 0; mf < 4; mf++) {
                const int crow = (64 * cg + 16 * mf + gr) * VS_STRIDE + 8 * ks + t4;
                const uint32_t a0 = __float_as_uint(Vs[crow]);
                const uint32_t a1 = __float_as_uint(Vs[crow + 8 * VS_STRIDE]);
                const uint32_t a2 = __float_as_uint(Vs[crow + 4]);
                const uint32_t a3 = __float_as_uint(Vs[crow + 8 * VS_STRIDE + 4]);
                mma_tf32(d[mf][0][0], d[mf][0][1], d[mf][0][2], d[mf][0][3],
                         a0, a1, a2, a3, __float_as_uint(b0a.x), __float_as_uint(b1a.x));
                mma_tf32(d[mf][1][0], d[mf][1][1], d[mf][1][2], d[mf][1][3],
                         a0, a1, a2, a3, __float_as_uint(b0a.y), __float_as_uint(b1a.y));
                mma_tf32(d[mf][2][0], d[mf][2][1], d[mf][2][2], d[mf][2][3],
                         a0, a1, a2, a3, __float_as_uint(b0a.z), __float_as_uint(b1a.z));
                mma_tf32(d[mf][3][0], d[mf][3][1], d[mf][3][2], d[mf][3][3],
                         a0, a1, a2, a3, __float_as_uint(b0a.w), __float_as_uint(b1a.w));
                mma_tf32(d[mf][4][0], d[mf][4][1], d[mf][4][2], d[mf][4][3],
                         a0, a1, a2, a3, __float_as_uint(b0b.x), __float_as_uint(b1b.x));
                mma_tf32(d[mf][5][0], d[mf][5][1], d[mf][5][2], d[mf][5][3],
                         a0, a1, a2, a3, __float_as_uint(b0b.y), __float_as_uint(b1b.y));
                mma_tf32(d[mf][6][0], d[mf][6][1], d[mf][6][2], d[mf][6][3],
                         a0, a1, a2, a3, __float_as_uint(b0b.z), __float_as_uint(b1b.z));
                mma_tf32(d[mf][7][0], d[mf][7][1], d[mf][7][2], d[mf][7][3],
                         a0, a1, a2, a3, __float_as_uint(b0b.w), __float_as_uint(b1b.w));
            }
        }
    }

    // --- epilogue: l broadcast + O^T/l -> g_attn_out[b][c][n] ---
    l0 += __shfl_xor_sync(0xffffffffu, l0, 1);
    l0 += __shfl_xor_sync(0xffffffffu, l0, 2);
    l1 += __shfl_xor_sync(0xffffffffu, l1, 1);
    l1 += __shfl_xor_sync(0xffffffffu, l1, 2);
    if (t4 == 0) {
        l_sm[16 * w + gr]     = l0;
        l_sm[16 * w + gr + 8] = l1;
    }
    __syncthreads();

    float* ob = g_attn_out + (size_t)b * C_IN * N_SP;
#pragma unroll
    for (int nf = 0; nf < 8; nf++) {
        const int q0 = 64 * qg + 8 * nf + 2 * t4;
        const float li0 = 1.f / l_sm[q0];
        const float li1 = 1.f / l_sm[q0 + 1];
#pragma unroll
        for (int mf = 0; mf < 4; mf++) {
            const int c0 = 64 * cg + 16 * mf + gr;
            float2 w0 = make_float2(d[mf][nf][0] * li0, d[mf][nf][1] * li1);
            float2 w1 = make_float2(d[mf][nf][2] * li0, d[mf][nf][3] * li1);
            *(float2*)&ob[(size_t)c0 * N_SP + n0 + q0]       = w0;
            *(float2*)&ob[(size_t)(c0 + 8) * N_SP + n0 + q0] = w1;
        }
    }
}

// ---------------------------------------------------------------------------
// Kernel 3: output projection (scalar fp32).
// ---------------------------------------------------------------------------
__global__ __launch_bounds__(256) void proj_kernel(const float* __restrict__ Wp)
{
    __shared__ float Wt[32 * 33];
    __shared__ float Xt[32 * 68];

    const int b  = blockIdx.z;
    const int ot = blockIdx.y;
    const int n0 = blockIdx.x * 64;

    const float* W  = Wp + ot * 32 * C_IN;
    const float* xb = g_attn_out + (size_t)b * C_IN * N_SP;
    float* dst      = g_proj + (size_t)b * C_IN * N_SP + (size_t)ot * 32 * N_SP;

    const int t = threadIdx.x, lane = t & 31, warp = t >> 5;

    float acc[8];
#pragma unroll
    for (int i = 0; i < 8; i++) acc[i] = 0.f;

    for (int c0 = 0; c0 < C_IN; c0 += 32) {
        for (int i = t; i < 1024; i += 256) {
            int o = i >> 5, c = i & 31;
            Wt[o * 33 + c] = W[o * C_IN + c0 + c];
        }
        for (int i = t; i < 2048; i += 256) {
            int c = i >> 6, n = i & 63;
            Xt[c * 68 + n] = xb[(size_t)(c0 + c) * N_SP + n0 + n];
        }
        __syncthreads();
#pragma unroll
        for (int c = 0; c < 32; c++) {
            float wv = Wt[lane * 33 + c];
            const float4 xv0 = *(const float4*)&Xt[c * 68 + warp * 8];
            const float4 xv1 = *(const float4*)&Xt[c * 68 + warp * 8 + 4];
            acc[0] += wv * xv0.x; acc[1] += wv * xv0.y;
            acc[2] += wv * xv0.z; acc[3] += wv * xv0.w;
            acc[4] += wv * xv1.x; acc[5] += wv * xv1.y;
            acc[6] += wv * xv1.z; acc[7] += wv * xv1.w;
        }
        __syncthreads();
    }
    float* drow = dst + (size_t)lane * N_SP + n0 + warp * 8;
    *(float4*)(drow)     = make_float4(acc[0], acc[1], acc[2], acc[3]);
    *(float4*)(drow + 4) = make_float4(acc[4], acc[5], acc[6], acc[7]);
}

// ---------------------------------------------------------------------------
// Kernel 4: InstanceNorm + residual.
// ---------------------------------------------------------------------------
__global__ __launch_bounds__(256) void norm_kernel(
    const float* __restrict__ x,
    float* __restrict__ att_out)
{
    __shared__ float red[16];

    const size_t bc = blockIdx.x;
    const float4* p4 = (const float4*)(g_proj + bc * N_SP);
    const float4* x4 = (const float4*)(x + bc * N_SP);
    float4* o4       = (float4*)(att_out + bc * N_SP);

    const int t = threadIdx.x, lane = t & 31, warp = t >> 5;

    float4 vals[4];
    float s = 0.f, sq = 0.f;
#pragma unroll
    for (int i = 0; i < 4; i++) {
        float4 v = p4[i * 256 + t];
        vals[i] = v;
        s  += v.x + v.y + v.z + v.w;
        sq += v.x * v.x + v.y * v.y + v.z * v.z + v.w * v.w;
    }
#pragma unroll
    for (int off = 16; off; off >>= 1) {
        s  += __shfl_xor_sync(0xffffffffu, s, off);
        sq += __shfl_xor_sync(0xffffffffu, sq, off);
    }
    if (lane == 0) { red[warp] = s; red[8 + warp] = sq; }
    __syncthreads();
    if (t == 0) {
        float ts = 0.f, tq = 0.f;
        for (int i = 0; i < 8; i++) { ts += red[i]; tq += red[8 + i]; }
        red[0] = ts; red[8] = tq;
    }
    __syncthreads();

    const float mean = red[0] * (1.f / N_SP);
    float var = red[8] * (1.f / N_SP) - mean * mean;
    const float rstd = rsqrtf(var + 1e-5f);

#pragma unroll
    for (int i = 0; i < 4; i++) {
        float4 v  = vals[i];
        float4 xr = x4[i * 256 + t];
        float4 r;
        r.x = (v.x - mean) * rstd + xr.x;
        r.y = (v.y - mean) * rstd + xr.y;
        r.z = (v.z - mean) * rstd + xr.z;
        r.w = (v.w - mean) * rstd + xr.w;
        o4[i * 256 + t] = r;
    }
}

// ---------------------------------------------------------------------------
extern "C" void kernel_launch(void* const* d_in, const int* in_sizes, int n_in,
                              void* d_out, int out_size)
{
    const float* x  = (const float*)d_in[0];
    const float* Wq = (const float*)d_in[1];
    const float* Wk = (const float*)d_in[2];
    const float* Wv = (const float*)d_in[3];
    const float* Wp = (const float*)d_in[4];
    float* out = (float*)d_out;

    cudaFuncSetAttribute(attn_kernel, cudaFuncAttributeMaxDynamicSharedMemorySize,
                         ATTN_SMEM_BYTES);

    qkv_kernel<<<dim3(64, 10, BATCH), 256>>>(x, Wq, Wk, Wv, out);
    attn_kernel<<<dim3(N_SP / 128, BATCH), 256, ATTN_SMEM_BYTES>>>(
        out + Q_OFF, out + K_OFF, out + V_OFF);
    proj_kernel<<<dim3(64, 8, BATCH), 256>>>(Wp);
    norm_kernel<<<BATCH * C_IN, 256>>>(x, out + A_OFF);
}

// round 7
// speedup vs baseline: 7.3031x; 1.3854x over previous
#include <cuda_runtime.h>
#include <math.h>
#include <stdint.h>

#define N_SP 4096
#define C_IN 256
#define CQ   32
#define BATCH 4

// d_out layout (floats): q[0], k[524288], v[1048576], attended[5242880]
#define Q_OFF 0
#define K_OFF 524288
#define V_OFF 1048576
#define A_OFF 5242880

// Scratch (device globals: allowed; no dynamic allocation)
__device__ float g_attn_out[BATCH * C_IN * N_SP];  // 16 MB
__device__ float g_proj[BATCH * C_IN * N_SP];      // 16 MB

// ---------------------------------------------------------------------------
// mma.sync tf32 helpers (sm_80+ generic PTX -> legal at compute_103)
// ---------------------------------------------------------------------------
__device__ __forceinline__ uint32_t f2tf32(float f) {
    uint32_t r;
    asm("cvt.rna.tf32.f32 %0, %1;" : "=r"(r) : "f"(f));
    return r;
}
__device__ __forceinline__ void mma_tf32(
    float& d0, float& d1, float& d2, float& d3,
    uint32_t a0, uint32_t a1, uint32_t a2, uint32_t a3,
    uint32_t b0, uint32_t b1)
{
    asm volatile(
        "mma.sync.aligned.m16n8k8.row.col.f32.tf32.tf32.f32 "
        "{%0,%1,%2,%3}, {%4,%5,%6,%7}, {%8,%9}, {%0,%1,%2,%3};"
        : "+f"(d0), "+f"(d1), "+f"(d2), "+f"(d3)
        : "r"(a0), "r"(a1), "r"(a2), "r"(a3), "r"(b0), "r"(b1));
}

// ---------------------------------------------------------------------------
// Unified channel GEMM on tensor cores (tf32):
//   dst[r][n] = sum_c W[r][c] * X[c][n],  K = 256
// CTA: 256 threads (8 warps as 2m x 4n), tile M=64, N=256, K-step 32.
// mode 0 (qkv): virtual W = [Wq;Wk;Wv] (320 rows, 5 m-tiles), X = x[b],
//               rows scatter to q/k/v regions of d_out.
// mode 1 (proj): W = Wp (256 rows, 4 m-tiles), X = g_attn_out[b], dst g_proj.
// SMEM: Ws[64][36] (9216 B) + Xs[32][264] (33792 B) = 43008 B static.
// Bank math: A-frag addr = gr*36 + t4 -> bank 4*gr+t4 (32 distinct);
//            B-frag addr = t4*264 + gr -> bank 8*t4+gr (32 distinct).
// ---------------------------------------------------------------------------
#define WS_STRIDE 36
#define XS_STRIDE 264

__global__ __launch_bounds__(256) void gemm_kernel(
    int mode,
    const float* __restrict__ x,
    const float* __restrict__ Wq,
    const float* __restrict__ Wk,
    const float* __restrict__ Wv,
    float* __restrict__ out)
{
    __shared__ float Ws[64 * WS_STRIDE];
    __shared__ float Xs[32 * XS_STRIDE];

    const int b  = blockIdx.z;
    const int mt = blockIdx.y;           // m-tile (64 rows)
    const int n0 = blockIdx.x * 256;

    const int t    = threadIdx.x;
    const int w    = t >> 5;
    const int lane = t & 31;
    const int gr   = lane >> 2;          // 0..7
    const int t4   = lane & 3;           // 0..3
    const int wm   = w >> 2;             // 0..1 (32-row half)
    const int wn   = w & 3;              // 0..3 (64-col quarter)

    const float* xb = (mode == 0) ? (x + (size_t)b * C_IN * N_SP)
                                  : (g_attn_out + (size_t)b * C_IN * N_SP);

    float d[2][8][4];
#pragma unroll
    for (int mf = 0; mf < 2; mf++)
#pragma unroll
        for (int nf = 0; nf < 8; nf++)
#pragma unroll
            for (int j = 0; j < 4; j++) d[mf][nf][j] = 0.f;

    // staging assignments
    const int wrow = t >> 2;             // 0..63 (W row within tile)
    const int wcol = (t & 3) * 8;        // 0,8,16,24

    for (int c0 = 0; c0 < C_IN; c0 += 32) {
        __syncthreads();
        // --- stage W tile [64 rows][32 c] ---
        {
            const int r = mt * 64 + wrow;       // global W row
            const float* wp;
            if (mode == 1)      wp = Wq + (size_t)r * C_IN;          // Wq slot = Wp
            else if (r < 32)    wp = Wq + (size_t)r * C_IN;
            else if (r < 64)    wp = Wk + (size_t)(r - 32) * C_IN;
            else                wp = Wv + (size_t)(r - 64) * C_IN;
            float4 w0 = *(const float4*)&wp[c0 + wcol];
            float4 w1 = *(const float4*)&wp[c0 + wcol + 4];
            w0.x = __uint_as_float(f2tf32(w0.x)); w0.y = __uint_as_float(f2tf32(w0.y));
            w0.z = __uint_as_float(f2tf32(w0.z)); w0.w = __uint_as_float(f2tf32(w0.w));
            w1.x = __uint_as_float(f2tf32(w1.x)); w1.y = __uint_as_float(f2tf32(w1.y));
            w1.z = __uint_as_float(f2tf32(w1.z)); w1.w = __uint_as_float(f2tf32(w1.w));
            *(float4*)&Ws[wrow * WS_STRIDE + wcol]     = w0;
            *(float4*)&Ws[wrow * WS_STRIDE + wcol + 4] = w1;
        }
        // --- stage X tile [32 c][256 n] ---
#pragma unroll
        for (int i = 0; i < 8; i++) {
            const int f  = t + 256 * i;          // float4 index (2048 total)
            const int c  = f >> 6;               // 0..31
            const int j4 = f & 63;               // 0..63
            float4 xv = *(const float4*)&xb[(size_t)(c0 + c) * N_SP + n0 + 4 * j4];
            xv.x = __uint_as_float(f2tf32(xv.x)); xv.y = __uint_as_float(f2tf32(xv.y));
            xv.z = __uint_as_float(f2tf32(xv.z)); xv.w = __uint_as_float(f2tf32(xv.w));
            *(float4*)&Xs[c * XS_STRIDE + 4 * j4] = xv;
        }
        __syncthreads();

#pragma unroll
        for (int ks = 0; ks < 4; ks++) {
            const int kk = 8 * ks;
            uint32_t a[2][4];
#pragma unroll
            for (int mf = 0; mf < 2; mf++) {
                const int r0 = (32 * wm + 16 * mf + gr) * WS_STRIDE + kk + t4;
                a[mf][0] = __float_as_uint(Ws[r0]);
                a[mf][1] = __float_as_uint(Ws[r0 + 8 * WS_STRIDE]);
                a[mf][2] = __float_as_uint(Ws[r0 + 4]);
                a[mf][3] = __float_as_uint(Ws[r0 + 8 * WS_STRIDE + 4]);
            }
#pragma unroll
            for (int nf = 0; nf < 8; nf++) {
                const int nc = 64 * wn + 8 * nf + gr;
                const uint32_t b0 = __float_as_uint(Xs[(kk + t4) * XS_STRIDE + nc]);
                const uint32_t b1 = __float_as_uint(Xs[(kk + t4 + 4) * XS_STRIDE + nc]);
                mma_tf32(d[0][nf][0], d[0][nf][1], d[0][nf][2], d[0][nf][3],
                         a[0][0], a[0][1], a[0][2], a[0][3], b0, b1);
                mma_tf32(d[1][nf][0], d[1][nf][1], d[1][nf][2], d[1][nf][3],
                         a[1][0], a[1][1], a[1][2], a[1][3], b0, b1);
            }
        }
    }

    // --- epilogue: scatter rows ---
#pragma unroll
    for (int mf = 0; mf < 2; mf++) {
#pragma unroll
        for (int rr = 0; rr < 2; rr++) {
            const int r = mt * 64 + 32 * wm + 16 * mf + gr + 8 * rr;
            float* dst;
            if (mode == 1)   dst = g_proj + ((size_t)b * C_IN + r) * N_SP;
            else if (r < 32) dst = out + Q_OFF + ((size_t)b * CQ + r) * N_SP;
            else if (r < 64) dst = out + K_OFF + ((size_t)b * CQ + (r - 32)) * N_SP;
            else             dst = out + V_OFF + ((size_t)b * C_IN + (r - 64)) * N_SP;
#pragma unroll
            for (int nf = 0; nf < 8; nf++) {
                const int nc = n0 + 64 * wn + 8 * nf + 2 * t4;
                *(float2*)&dst[nc] = make_float2(d[mf][nf][2 * rr], d[mf][nf][2 * rr + 1]);
            }
        }
    }
}

// ---------------------------------------------------------------------------
// Kernel 2: flash attention via mma.sync tf32.  (unchanged from R4 winner)
// ---------------------------------------------------------------------------
#define VS_STRIDE 132
#define KS_STRIDE 132
#define PT_STRIDE 136
#define VS_FLOATS (256 * VS_STRIDE)
#define KS_FLOATS (32 * KS_STRIDE)
#define PT_FLOATS (128 * PT_STRIDE)
#define ATTN_SMEM_BYTES ((VS_FLOATS + KS_FLOATS + PT_FLOATS) * 4)

__device__ __forceinline__ int pt_pos(int q) {
    return ((q >> 5) << 5) + ((q & 7) << 2) + ((q >> 3) & 3);
}

__global__ __launch_bounds__(256, 1) void attn_kernel(
    const float* __restrict__ qbuf,
    const float* __restrict__ kbuf,
    const float* __restrict__ vbuf)
{
    extern __shared__ float smem[];
    float* Vs = smem;
    float* Ks = smem + VS_FLOATS;
    float* Pt = smem + VS_FLOATS + KS_FLOATS;
    __shared__ float l_sm[128];

    const int t    = threadIdx.x;
    const int w    = t >> 5;
    const int lane = t & 31;
    const int gr   = lane >> 2;
    const int t4   = lane & 3;

    const int b  = blockIdx.y;
    const int n0 = blockIdx.x * 128;
    const float scale = 0.1767766952966369f;  // 32^-0.5

    const float* q = qbuf + (size_t)b * CQ   * N_SP;
    const float* k = kbuf + (size_t)b * CQ   * N_SP;
    const float* v = vbuf + (size_t)b * C_IN * N_SP;

    uint32_t qa[4][4];
    {
        const int rA = n0 + 16 * w + gr;
        const int rB = rA + 8;
#pragma unroll
        for (int ks = 0; ks < 4; ks++) {
            const int c0 = 8 * ks + t4;
            qa[ks][0] = f2tf32(q[(size_t)c0 * N_SP + rA] * scale);
            qa[ks][1] = f2tf32(q[(size_t)c0 * N_SP + rB] * scale);
            qa[ks][2] = f2tf32(q[(size_t)(c0 + 4) * N_SP + rA] * scale);
            qa[ks][3] = f2tf32(q[(size_t)(c0 + 4) * N_SP + rB] * scale);
        }
    }

    const int cg = w & 3;
    const int qg = w >> 2;
    float d[4][8][4];
#pragma unroll
    for (int mf = 0; mf < 4; mf++)
#pragma unroll
        for (int nf = 0; nf < 8; nf++)
#pragma unroll
            for (int j = 0; j < 4; j++) d[mf][nf][j] = 0.f;

    float l0 = 0.f, l1 = 0.f;
    const int posA = pt_pos(16 * w + gr);
    const int posB = pt_pos(16 * w + gr + 8);

    for (int it = 0; it < 32; it++) {
        const int m0 = it * 128;
        __syncthreads();

#pragma unroll
        for (int i = 0; i < 4; i++) {
            const int fl = t + 256 * i;
            const int c  = fl >> 5;
            const int j  = fl & 31;
            float4 kv = *(const float4*)&k[(size_t)c * N_SP + m0 + 4 * j];
            kv.x = __uint_as_float(f2tf32(kv.x));
            kv.y = __uint_as_float(f2tf32(kv.y));
            kv.z = __uint_as_float(f2tf32(kv.z));
            kv.w = __uint_as_float(f2tf32(kv.w));
            *(float4*)&Ks[c * KS_STRIDE + 4 * j] = kv;
        }
#pragma unroll
        for (int i = 0; i < 32; i++) {
            const int fl = t + 256 * i;
            const int c  = fl >> 5;
            const int j  = fl & 31;
            float4 vv = *(const float4*)&v[(size_t)c * N_SP + m0 + 4 * j];
            vv.x = __uint_as_float(f2tf32(vv.x));
            vv.y = __uint_as_float(f2tf32(vv.y));
            vv.z = __uint_as_float(f2tf32(vv.z));
            vv.w = __uint_as_float(f2tf32(vv.w));
            *(float4*)&Vs[c * VS_STRIDE + 4 * j] = vv;
        }
        __syncthreads();

#pragma unroll
        for (int nf = 0; nf < 16; nf++) {
            float s0 = 0.f, s1 = 0.f, s2 = 0.f, s3 = 0.f;
#pragma unroll
            for (int ks = 0; ks < 4; ks++) {
                const uint32_t b0 = __float_as_uint(Ks[(8 * ks + t4) * KS_STRIDE + 8 * nf + gr]);
                const uint32_t b1 = __float_as_uint(Ks[(8 * ks + t4 + 4) * KS_STRIDE + 8 * nf + gr]);
                mma_tf32(s0, s1, s2, s3, qa[ks][0], qa[ks][1], qa[ks][2], qa[ks][3], b0, b1);
            }
            const float p0 = __expf(s0);
            const float p1 = __expf(s1);
            const float p2 = __expf(s2);
            const float p3 = __expf(s3);
            l0 += p0 + p1;
            l1 += p2 + p3;
            const int mrow = 8 * nf + 2 * t4;
            Pt[mrow * PT_STRIDE + posA]       = __uint_as_float(f2tf32(p0));
            Pt[(mrow + 1) * PT_STRIDE + posA] = __uint_as_float(f2tf32(p1));
            Pt[mrow * PT_STRIDE + posB]       = __uint_as_float(f2tf32(p2));
            Pt[(mrow + 1) * PT_STRIDE + posB] = __uint_as_float(f2tf32(p3));
        }
        __syncthreads();

#pragma unroll
        for (int ks = 0; ks < 16; ks++) {
            const float* pr0 = &Pt[(8 * ks + t4) * PT_STRIDE];
            const float* pr1 = &Pt[(8 * ks + t4 + 4) * PT_STRIDE];
            const float4 b0a = *(const float4*)&pr0[64 * qg + 4 * gr];
            const float4 b1a = *(const float4*)&pr1[64 * qg + 4 * gr];
            const float4 b0b = *(const float4*)&pr0[64 * qg + 32 + 4 * gr];
            const float4 b1b = *(const float4*)&pr1[64 * qg + 32 + 4 * gr];
#pragma unroll
            for (int mf = 0; mf < 4; mf++) {
                const int crow = (64 * cg + 16 * mf + gr) * VS_STRIDE + 8 * ks + t4;
                const uint32_t a0 = __float_as_uint(Vs[crow]);
                const uint32_t a1 = __float_as_uint(Vs[crow + 8 * VS_STRIDE]);
                const uint32_t a2 = __float_as_uint(Vs[crow + 4]);
                const uint32_t a3 = __float_as_uint(Vs[crow + 8 * VS_STRIDE + 4]);
                mma_tf32(d[mf][0][0], d[mf][0][1], d[mf][0][2], d[mf][0][3],
                         a0, a1, a2, a3, __float_as_uint(b0a.x), __float_as_uint(b1a.x));
                mma_tf32(d[mf][1][0], d[mf][1][1], d[mf][1][2], d[mf][1][3],
                         a0, a1, a2, a3, __float_as_uint(b0a.y), __float_as_uint(b1a.y));
                mma_tf32(d[mf][2][0], d[mf][2][1], d[mf][2][2], d[mf][2][3],
                         a0, a1, a2, a3, __float_as_uint(b0a.z), __float_as_uint(b1a.z));
                mma_tf32(d[mf][3][0], d[mf][3][1], d[mf][3][2], d[mf][3][3],
                         a0, a1, a2, a3, __float_as_uint(b0a.w), __float_as_uint(b1a.w));
                mma_tf32(d[mf][4][0], d[mf][4][1], d[mf][4][2], d[mf][4][3],
                         a0, a1, a2, a3, __float_as_uint(b0b.x), __float_as_uint(b1b.x));
                mma_tf32(d[mf][5][0], d[mf][5][1], d[mf][5][2], d[mf][5][3],
                         a0, a1, a2, a3, __float_as_uint(b0b.y), __float_as_uint(b1b.y));
                mma_tf32(d[mf][6][0], d[mf][6][1], d[mf][6][2], d[mf][6][3],
                         a0, a1, a2, a3, __float_as_uint(b0b.z), __float_as_uint(b1b.z));
                mma_tf32(d[mf][7][0], d[mf][7][1], d[mf][7][2], d[mf][7][3],
                         a0, a1, a2, a3, __float_as_uint(b0b.w), __float_as_uint(b1b.w));
            }
        }
    }

    l0 += __shfl_xor_sync(0xffffffffu, l0, 1);
    l0 += __shfl_xor_sync(0xffffffffu, l0, 2);
    l1 += __shfl_xor_sync(0xffffffffu, l1, 1);
    l1 += __shfl_xor_sync(0xffffffffu, l1, 2);
    if (t4 == 0) {
        l_sm[16 * w + gr]     = l0;
        l_sm[16 * w + gr + 8] = l1;
    }
    __syncthreads();

    float* ob = g_attn_out + (size_t)b * C_IN * N_SP;
#pragma unroll
    for (int nf = 0; nf < 8; nf++) {
        const int q0 = 64 * qg + 8 * nf + 2 * t4;
        const float li0 = 1.f / l_sm[q0];
        const float li1 = 1.f / l_sm[q0 + 1];
#pragma unroll
        for (int mf = 0; mf < 4; mf++) {
            const int c0 = 64 * cg + 16 * mf + gr;
            float2 w0 = make_float2(d[mf][nf][0] * li0, d[mf][nf][1] * li1);
            float2 w1 = make_float2(d[mf][nf][2] * li0, d[mf][nf][3] * li1);
            *(float2*)&ob[(size_t)c0 * N_SP + n0 + q0]       = w0;
            *(float2*)&ob[(size_t)(c0 + 8) * N_SP + n0 + q0] = w1;
        }
    }
}

// ---------------------------------------------------------------------------
// Kernel 4: InstanceNorm + residual.
// ---------------------------------------------------------------------------
__global__ __launch_bounds__(256) void norm_kernel(
    const float* __restrict__ x,
    float* __restrict__ att_out)
{
    __shared__ float red[16];

    const size_t bc = blockIdx.x;
    const float4* p4 = (const float4*)(g_proj + bc * N_SP);
    const float4* x4 = (const float4*)(x + bc * N_SP);
    float4* o4       = (float4*)(att_out + bc * N_SP);

    const int t = threadIdx.x, lane = t & 31, warp = t >> 5;

    float4 vals[4];
    float s = 0.f, sq = 0.f;
#pragma unroll
    for (int i = 0; i < 4; i++) {
        float4 v = p4[i * 256 + t];
        vals[i] = v;
        s  += v.x + v.y + v.z + v.w;
        sq += v.x * v.x + v.y * v.y + v.z * v.z + v.w * v.w;
    }
#pragma unroll
    for (int off = 16; off; off >>= 1) {
        s  += __shfl_xor_sync(0xffffffffu, s, off);
        sq += __shfl_xor_sync(0xffffffffu, sq, off);
    }
    if (lane == 0) { red[warp] = s; red[8 + warp] = sq; }
    __syncthreads();
    if (t == 0) {
        float ts = 0.f, tq = 0.f;
        for (int i = 0; i < 8; i++) { ts += red[i]; tq += red[8 + i]; }
        red[0] = ts; red[8] = tq;
    }
    __syncthreads();

    const float mean = red[0] * (1.f / N_SP);
    float var = red[8] * (1.f / N_SP) - mean * mean;
    const float rstd = rsqrtf(var + 1e-5f);

#pragma unroll
    for (int i = 0; i < 4; i++) {
        float4 v  = vals[i];
        float4 xr = x4[i * 256 + t];
        float4 r;
        r.x = (v.x - mean) * rstd + xr.x;
        r.y = (v.y - mean) * rstd + xr.y;
        r.z = (v.z - mean) * rstd + xr.z;
        r.w = (v.w - mean) * rstd + xr.w;
        o4[i * 256 + t] = r;
    }
}

// ---------------------------------------------------------------------------
extern "C" void kernel_launch(void* const* d_in, const int* in_sizes, int n_in,
                              void* d_out, int out_size)
{
    const float* x  = (const float*)d_in[0];
    const float* Wq = (const float*)d_in[1];
    const float* Wk = (const float*)d_in[2];
    const float* Wv = (const float*)d_in[3];
    const float* Wp = (const float*)d_in[4];
    float* out = (float*)d_out;

    cudaFuncSetAttribute(attn_kernel, cudaFuncAttributeMaxDynamicSharedMemorySize,
                         ATTN_SMEM_BYTES);

    // qkv: virtual 320-row weight [Wq;Wk;Wv], 5 m-tiles of 64
    gemm_kernel<<<dim3(16, 5, BATCH), 256>>>(0, x, Wq, Wk, Wv, out);
    attn_kernel<<<dim3(N_SP / 128, BATCH), 256, ATTN_SMEM_BYTES>>>(
        out + Q_OFF, out + K_OFF, out + V_OFF);
    // proj: Wp in the Wq slot, 4 m-tiles of 64
    gemm_kernel<<<dim3(16, 4, BATCH), 256>>>(1, nullptr, Wp, nullptr, nullptr, out);
    norm_kernel<<<BATCH * C_IN, 256>>>(x, out + A_OFF);
}

// round 8
// speedup vs baseline: 12.3625x; 1.6928x over previous
#include <cuda_runtime.h>
#include <cuda_fp16.h>
#include <math.h>
#include <stdint.h>

#define N_SP 4096
#define C_IN 256
#define CQ   32
#define BATCH 4

// d_out layout (floats): q[0], k[524288], v[1048576], attended[5242880]
#define Q_OFF 0
#define K_OFF 524288
#define V_OFF 1048576
#define A_OFF 5242880

// Scratch (device globals: allowed; no dynamic allocation)
__device__ float g_attn_out[BATCH * C_IN * N_SP];  // 16 MB
__device__ float g_proj[BATCH * C_IN * N_SP];      // 16 MB

// ---------------------------------------------------------------------------
// mma.sync helpers (sm_80+ generic PTX -> legal at compute_103)
// ---------------------------------------------------------------------------
__device__ __forceinline__ uint32_t f2tf32(float f) {
    uint32_t r;
    asm("cvt.rna.tf32.f32 %0, %1;" : "=r"(r) : "f"(f));
    return r;
}
__device__ __forceinline__ void mma_tf32(
    float& d0, float& d1, float& d2, float& d3,
    uint32_t a0, uint32_t a1, uint32_t a2, uint32_t a3,
    uint32_t b0, uint32_t b1)
{
    asm volatile(
        "mma.sync.aligned.m16n8k8.row.col.f32.tf32.tf32.f32 "
        "{%0,%1,%2,%3}, {%4,%5,%6,%7}, {%8,%9}, {%0,%1,%2,%3};"
        : "+f"(d0), "+f"(d1), "+f"(d2), "+f"(d3)
        : "r"(a0), "r"(a1), "r"(a2), "r"(a3), "r"(b0), "r"(b1));
}
// fp16 m16n8k16, fp32 accumulate (same 11-bit significand class as tf32)
__device__ __forceinline__ void mma_f16(
    float& d0, float& d1, float& d2, float& d3,
    uint32_t a0, uint32_t a1, uint32_t a2, uint32_t a3,
    uint32_t b0, uint32_t b1)
{
    asm volatile(
        "mma.sync.aligned.m16n8k16.row.col.f32.f16.f16.f32 "
        "{%0,%1,%2,%3}, {%4,%5,%6,%7}, {%8,%9}, {%0,%1,%2,%3};"
        : "+f"(d0), "+f"(d1), "+f"(d2), "+f"(d3)
        : "r"(a0), "r"(a1), "r"(a2), "r"(a3), "r"(b0), "r"(b1));
}
__device__ __forceinline__ uint32_t h2u(__half2 h) {
    return *reinterpret_cast<uint32_t*>(&h);
}

// ---------------------------------------------------------------------------
// Unified channel GEMM on tensor cores (tf32). (unchanged R6 winner)
// ---------------------------------------------------------------------------
#define WS_STRIDE 36
#define XS_STRIDE 264

__global__ __launch_bounds__(256) void gemm_kernel(
    int mode,
    const float* __restrict__ x,
    const float* __restrict__ Wq,
    const float* __restrict__ Wk,
    const float* __restrict__ Wv,
    float* __restrict__ out)
{
    __shared__ float Ws[64 * WS_STRIDE];
    __shared__ float Xs[32 * XS_STRIDE];

    const int b  = blockIdx.z;
    const int mt = blockIdx.y;
    const int n0 = blockIdx.x * 256;

    const int t    = threadIdx.x;
    const int w    = t >> 5;
    const int lane = t & 31;
    const int gr   = lane >> 2;
    const int t4   = lane & 3;
    const int wm   = w >> 2;
    const int wn   = w & 3;

    const float* xb = (mode == 0) ? (x + (size_t)b * C_IN * N_SP)
                                  : (g_attn_out + (size_t)b * C_IN * N_SP);

    float d[2][8][4];
#pragma unroll
    for (int mf = 0; mf < 2; mf++)
#pragma unroll
        for (int nf = 0; nf < 8; nf++)
#pragma unroll
            for (int j = 0; j < 4; j++) d[mf][nf][j] = 0.f;

    const int wrow = t >> 2;
    const int wcol = (t & 3) * 8;

    for (int c0 = 0; c0 < C_IN; c0 += 32) {
        __syncthreads();
        {
            const int r = mt * 64 + wrow;
            const float* wp;
            if (mode == 1)      wp = Wq + (size_t)r * C_IN;
            else if (r < 32)    wp = Wq + (size_t)r * C_IN;
            else if (r < 64)    wp = Wk + (size_t)(r - 32) * C_IN;
            else                wp = Wv + (size_t)(r - 64) * C_IN;
            float4 w0 = *(const float4*)&wp[c0 + wcol];
            float4 w1 = *(const float4*)&wp[c0 + wcol + 4];
            w0.x = __uint_as_float(f2tf32(w0.x)); w0.y = __uint_as_float(f2tf32(w0.y));
            w0.z = __uint_as_float(f2tf32(w0.z)); w0.w = __uint_as_float(f2tf32(w0.w));
            w1.x = __uint_as_float(f2tf32(w1.x)); w1.y = __uint_as_float(f2tf32(w1.y));
            w1.z = __uint_as_float(f2tf32(w1.z)); w1.w = __uint_as_float(f2tf32(w1.w));
            *(float4*)&Ws[wrow * WS_STRIDE + wcol]     = w0;
            *(float4*)&Ws[wrow * WS_STRIDE + wcol + 4] = w1;
        }
#pragma unroll
        for (int i = 0; i < 8; i++) {
            const int f  = t + 256 * i;
            const int c  = f >> 6;
            const int j4 = f & 63;
            float4 xv = *(const float4*)&xb[(size_t)(c0 + c) * N_SP + n0 + 4 * j4];
            xv.x = __uint_as_float(f2tf32(xv.x)); xv.y = __uint_as_float(f2tf32(xv.y));
            xv.z = __uint_as_float(f2tf32(xv.z)); xv.w = __uint_as_float(f2tf32(xv.w));
            *(float4*)&Xs[c * XS_STRIDE + 4 * j4] = xv;
        }
        __syncthreads();

#pragma unroll
        for (int ks = 0; ks < 4; ks++) {
            const int kk = 8 * ks;
            uint32_t a[2][4];
#pragma unroll
            for (int mf = 0; mf < 2; mf++) {
                const int r0 = (32 * wm + 16 * mf + gr) * WS_STRIDE + kk + t4;
                a[mf][0] = __float_as_uint(Ws[r0]);
                a[mf][1] = __float_as_uint(Ws[r0 + 8 * WS_STRIDE]);
                a[mf][2] = __float_as_uint(Ws[r0 + 4]);
                a[mf][3] = __float_as_uint(Ws[r0 + 8 * WS_STRIDE + 4]);
            }
#pragma unroll
            for (int nf = 0; nf < 8; nf++) {
                const int nc = 64 * wn + 8 * nf + gr;
                const uint32_t b0 = __float_as_uint(Xs[(kk + t4) * XS_STRIDE + nc]);
                const uint32_t b1 = __float_as_uint(Xs[(kk + t4 + 4) * XS_STRIDE + nc]);
                mma_tf32(d[0][nf][0], d[0][nf][1], d[0][nf][2], d[0][nf][3],
                         a[0][0], a[0][1], a[0][2], a[0][3], b0, b1);
                mma_tf32(d[1][nf][0], d[1][nf][1], d[1][nf][2], d[1][nf][3],
                         a[1][0], a[1][1], a[1][2], a[1][3], b0, b1);
            }
        }
    }

#pragma unroll
    for (int mf = 0; mf < 2; mf++) {
#pragma unroll
        for (int rr = 0; rr < 2; rr++) {
            const int r = mt * 64 + 32 * wm + 16 * mf + gr + 8 * rr;
            float* dst;
            if (mode == 1)   dst = g_proj + ((size_t)b * C_IN + r) * N_SP;
            else if (r < 32) dst = out + Q_OFF + ((size_t)b * CQ + r) * N_SP;
            else if (r < 64) dst = out + K_OFF + ((size_t)b * CQ + (r - 32)) * N_SP;
            else             dst = out + V_OFF + ((size_t)b * C_IN + (r - 64)) * N_SP;
#pragma unroll
            for (int nf = 0; nf < 8; nf++) {
                const int nc = n0 + 64 * wn + 8 * nf + 2 * t4;
                *(float2*)&dst[nc] = make_float2(d[mf][nf][2 * rr], d[mf][nf][2 * rr + 1]);
            }
        }
    }
}

// ---------------------------------------------------------------------------
// Kernel 2: flash attention via mma.sync fp16 (m16n8k16), fp32 accumulate.
// Grid (32 q-tiles, 4 batch). CTA = 256 threads = 8 warps, 1 CTA/SM.
//
// half2 smem layouts (addr units = half2 = 4B; bank = addr mod 32):
//  Vsp[c][m2]  stride 68 : Vsp[c][m2] = (V[c][2m2], V[c][2m2+1])
//  Ksp[c2][m]  stride 136: Ksp[c2][m] = (K[2c2][m], K[2c2+1][m])
//  Ptp[q][m2]  stride 68 : Ptp[q][m2] = (P[q][2m2], P[q][2m2+1])
// GEMM1: S[q][m] = Q*K^T, 2 k16-steps. exp (no max; s bounded), l in fp32,
//        pack adjacent-m pairs -> Ptp (conflict-free, bank 4gr+t4).
// GEMM2: O^T[c][q] += V * P^T, 8 k16-steps; A from Vsp (bank 4gr+t4),
//        B from Ptp (bank 4gr+t4). O in 128 fp32 regs across all tiles.
// ---------------------------------------------------------------------------
#define SV 68
#define SK 136
#define SP 68
#define VSP_ELEMS (256 * SV)
#define KSP_ELEMS (16 * SK)
#define PTP_ELEMS (128 * SP)
#define ATTN_SMEM_BYTES ((VSP_ELEMS + KSP_ELEMS + PTP_ELEMS) * 4)

__global__ __launch_bounds__(256, 1) void attn_kernel(
    const float* __restrict__ qbuf,
    const float* __restrict__ kbuf,
    const float* __restrict__ vbuf)
{
    extern __shared__ __half2 smemh[];
    __half2* Vsp = smemh;
    __half2* Ksp = smemh + VSP_ELEMS;
    __half2* Ptp = smemh + VSP_ELEMS + KSP_ELEMS;
    __shared__ float l_sm[128];

    const int t    = threadIdx.x;
    const int w    = t >> 5;
    const int lane = t & 31;
    const int gr   = lane >> 2;
    const int t4   = lane & 3;

    const int b  = blockIdx.y;
    const int n0 = blockIdx.x * 128;
    const float scale = 0.1767766952966369f;  // 32^-0.5

    const float* q = qbuf + (size_t)b * CQ   * N_SP;
    const float* k = kbuf + (size_t)b * CQ   * N_SP;
    const float* v = vbuf + (size_t)b * C_IN * N_SP;

    // --- Q fragments (persistent, fp16): 2 k16-steps ---
    uint32_t qa[2][4];
    {
        const int rA = n0 + 16 * w + gr;
        const int rB = rA + 8;
#pragma unroll
        for (int ks = 0; ks < 2; ks++) {
            const int c0 = 16 * ks + 2 * t4;
            qa[ks][0] = h2u(__floats2half2_rn(q[(size_t)c0 * N_SP + rA] * scale,
                                              q[(size_t)(c0 + 1) * N_SP + rA] * scale));
            qa[ks][1] = h2u(__floats2half2_rn(q[(size_t)c0 * N_SP + rB] * scale,
                                              q[(size_t)(c0 + 1) * N_SP + rB] * scale));
            qa[ks][2] = h2u(__floats2half2_rn(q[(size_t)(c0 + 8) * N_SP + rA] * scale,
                                              q[(size_t)(c0 + 9) * N_SP + rA] * scale));
            qa[ks][3] = h2u(__floats2half2_rn(q[(size_t)(c0 + 8) * N_SP + rB] * scale,
                                              q[(size_t)(c0 + 9) * N_SP + rB] * scale));
        }
    }

    const int cg = w & 3;
    const int qg = w >> 2;
    float d[4][8][4];
#pragma unroll
    for (int mf = 0; mf < 4; mf++)
#pragma unroll
        for (int nf = 0; nf < 8; nf++)
#pragma unroll
            for (int j = 0; j < 4; j++) d[mf][nf][j] = 0.f;

    float l0 = 0.f, l1 = 0.f;

    for (int it = 0; it < 32; it++) {
        const int m0 = it * 128;
        __syncthreads();  // previous tile fully consumed before restaging

        // --- stage K tile -> Ksp[c2][m] ---
        {
            const int c2 = t >> 4;            // 0..15
            const int mb = (t & 15) * 8;      // 0..120
            const float* r0 = &k[(size_t)(2 * c2) * N_SP + m0 + mb];
            const float* r1 = &k[(size_t)(2 * c2 + 1) * N_SP + m0 + mb];
            float4 x0 = *(const float4*)r0;
            float4 x1 = *(const float4*)(r0 + 4);
            float4 y0 = *(const float4*)r1;
            float4 y1 = *(const float4*)(r1 + 4);
            __half2* dst = &Ksp[c2 * SK + mb];
            dst[0] = __floats2half2_rn(x0.x, y0.x);
            dst[1] = __floats2half2_rn(x0.y, y0.y);
            dst[2] = __floats2half2_rn(x0.z, y0.z);
            dst[3] = __floats2half2_rn(x0.w, y0.w);
            dst[4] = __floats2half2_rn(x1.x, y1.x);
            dst[5] = __floats2half2_rn(x1.y, y1.y);
            dst[6] = __floats2half2_rn(x1.z, y1.z);
            dst[7] = __floats2half2_rn(x1.w, y1.w);
        }
        // --- stage V tile -> Vsp[c][m2] (coalesced gmem, adjacent-m pairs) ---
#pragma unroll
        for (int i = 0; i < 32; i++) {
            const int fl = t + 256 * i;
            const int c  = fl >> 5;
            const int j  = fl & 31;
            const float4 vv = *(const float4*)&v[(size_t)c * N_SP + m0 + 4 * j];
            Vsp[c * SV + 2 * j]     = __floats2half2_rn(vv.x, vv.y);
            Vsp[c * SV + 2 * j + 1] = __floats2half2_rn(vv.z, vv.w);
        }
        __syncthreads();

        // --- GEMM1 + softmax + Ptp store ---
#pragma unroll
        for (int nf = 0; nf < 16; nf++) {
            float s0 = 0.f, s1 = 0.f, s2 = 0.f, s3 = 0.f;
            const int m = 8 * nf + gr;
#pragma unroll
            for (int ks = 0; ks < 2; ks++) {
                const uint32_t b0 = h2u(Ksp[(t4 + 8 * ks) * SK + m]);
                const uint32_t b1 = h2u(Ksp[(t4 + 4 + 8 * ks) * SK + m]);
                mma_f16(s0, s1, s2, s3, qa[ks][0], qa[ks][1], qa[ks][2], qa[ks][3], b0, b1);
            }
            const float p0 = __expf(s0);
            const float p1 = __expf(s1);
            const float p2 = __expf(s2);
            const float p3 = __expf(s3);
            l0 += p0 + p1;
            l1 += p2 + p3;
            const int m2 = 4 * nf + t4;
            Ptp[(16 * w + gr) * SP + m2]     = __floats2half2_rn(p0, p1);
            Ptp[(16 * w + gr + 8) * SP + m2] = __floats2half2_rn(p2, p3);
        }
        __syncthreads();

        // --- GEMM2: O^T += V * P^T (8 k16-steps) ---
#pragma unroll
        for (int ks = 0; ks < 8; ks++) {
            uint32_t bb[8][2];
#pragma unroll
            for (int nf = 0; nf < 8; nf++) {
                const int qq = 64 * qg + 8 * nf + gr;
                bb[nf][0] = h2u(Ptp[qq * SP + t4 + 8 * ks]);
                bb[nf][1] = h2u(Ptp[qq * SP + t4 + 4 + 8 * ks]);
            }
#pragma unroll
            for (int mf = 0; mf < 4; mf++) {
                const int c0 = 64 * cg + 16 * mf + gr;
                const uint32_t a0 = h2u(Vsp[c0 * SV + t4 + 8 * ks]);
                const uint32_t a1 = h2u(Vsp[(c0 + 8) * SV + t4 + 8 * ks]);
                const uint32_t a2 = h2u(Vsp[c0 * SV + t4 + 4 + 8 * ks]);
                const uint32_t a3 = h2u(Vsp[(c0 + 8) * SV + t4 + 4 + 8 * ks]);
#pragma unroll
                for (int nf = 0; nf < 8; nf++) {
                    mma_f16(d[mf][nf][0], d[mf][nf][1], d[mf][nf][2], d[mf][nf][3],
                            a0, a1, a2, a3, bb[nf][0], bb[nf][1]);
                }
            }
        }
    }

    // --- epilogue: l broadcast + O^T/l -> g_attn_out[b][c][n] ---
    l0 += __shfl_xor_sync(0xffffffffu, l0, 1);
    l0 += __shfl_xor_sync(0xffffffffu, l0, 2);
    l1 += __shfl_xor_sync(0xffffffffu, l1, 1);
    l1 += __shfl_xor_sync(0xffffffffu, l1, 2);
    if (t4 == 0) {
        l_sm[16 * w + gr]     = l0;
        l_sm[16 * w + gr + 8] = l1;
    }
    __syncthreads();

    float* ob = g_attn_out + (size_t)b * C_IN * N_SP;
#pragma unroll
    for (int nf = 0; nf < 8; nf++) {
        const int q0 = 64 * qg + 8 * nf + 2 * t4;
        const float li0 = 1.f / l_sm[q0];
        const float li1 = 1.f / l_sm[q0 + 1];
#pragma unroll
        for (int mf = 0; mf < 4; mf++) {
            const int c0 = 64 * cg + 16 * mf + gr;
            float2 w0 = make_float2(d[mf][nf][0] * li0, d[mf][nf][1] * li1);
            float2 w1 = make_float2(d[mf][nf][2] * li0, d[mf][nf][3] * li1);
            *(float2*)&ob[(size_t)c0 * N_SP + n0 + q0]       = w0;
            *(float2*)&ob[(size_t)(c0 + 8) * N_SP + n0 + q0] = w1;
        }
    }
}

// ---------------------------------------------------------------------------
// Kernel 4: InstanceNorm + residual. (unchanged)
// ---------------------------------------------------------------------------
__global__ __launch_bounds__(256) void norm_kernel(
    const float* __restrict__ x,
    float* __restrict__ att_out)
{
    __shared__ float red[16];

    const size_t bc = blockIdx.x;
    const float4* p4 = (const float4*)(g_proj + bc * N_SP);
    const float4* x4 = (const float4*)(x + bc * N_SP);
    float4* o4       = (float4*)(att_out + bc * N_SP);

    const int t = threadIdx.x, lane = t & 31, warp = t >> 5;

    float4 vals[4];
    float s = 0.f, sq = 0.f;
#pragma unroll
    for (int i = 0; i < 4; i++) {
        float4 v = p4[i * 256 + t];
        vals[i] = v;
        s  += v.x + v.y + v.z + v.w;
        sq += v.x * v.x + v.y * v.y + v.z * v.z + v.w * v.w;
    }
#pragma unroll
    for (int off = 16; off; off >>= 1) {
        s  += __shfl_xor_sync(0xffffffffu, s, off);
        sq += __shfl_xor_sync(0xffffffffu, sq, off);
    }
    if (lane == 0) { red[warp] = s; red[8 + warp] = sq; }
    __syncthreads();
    if (t == 0) {
        float ts = 0.f, tq = 0.f;
        for (int i = 0; i < 8; i++) { ts += red[i]; tq += red[8 + i]; }
        red[0] = ts; red[8] = tq;
    }
    __syncthreads();

    const float mean = red[0] * (1.f / N_SP);
    float var = red[8] * (1.f / N_SP) - mean * mean;
    const float rstd = rsqrtf(var + 1e-5f);

#pragma unroll
    for (int i = 0; i < 4; i++) {
        float4 v  = vals[i];
        float4 xr = x4[i * 256 + t];
        float4 r;
        r.x = (v.x - mean) * rstd + xr.x;
        r.y = (v.y - mean) * rstd + xr.y;
        r.z = (v.z - mean) * rstd + xr.z;
        r.w = (v.w - mean) * rstd + xr.w;
        o4[i * 256 + t] = r;
    }
}

// ---------------------------------------------------------------------------
extern "C" void kernel_launch(void* const* d_in, const int* in_sizes, int n_in,
                              void* d_out, int out_size)
{
    const float* x  = (const float*)d_in[0];
    const float* Wq = (const float*)d_in[1];
    const float* Wk = (const float*)d_in[2];
    const float* Wv = (const float*)d_in[3];
    const float* Wp = (const float*)d_in[4];
    float* out = (float*)d_out;

    cudaFuncSetAttribute(attn_kernel, cudaFuncAttributeMaxDynamicSharedMemorySize,
                         ATTN_SMEM_BYTES);

    gemm_kernel<<<dim3(16, 5, BATCH), 256>>>(0, x, Wq, Wk, Wv, out);
    attn_kernel<<<dim3(N_SP / 128, BATCH), 256, ATTN_SMEM_BYTES>>>(
        out + Q_OFF, out + K_OFF, out + V_OFF);
    gemm_kernel<<<dim3(16, 4, BATCH), 256>>>(1, nullptr, Wp, nullptr, nullptr, out);
    norm_kernel<<<BATCH * C_IN, 256>>>(x, out + A_OFF);
}